// round 2
// baseline (speedup 1.0000x reference)
#include <cuda_runtime.h>
#include <cstdint>

#define B_SZ   32
#define RESN   100
#define ITERS  1000
#define KSPLIT 8          // fc4 k-dim split
#define CSIZE  4          // cluster CTAs per sample
#define RPC    25         // rows per CTA

// -------- scratch (device globals; no allocation allowed) ----------
__device__ float g_h1[B_SZ * 128];
__device__ float g_h2[B_SZ * 256];
__device__ float g_h3[B_SZ * 512];
__device__ float g_part[KSPLIT * B_SZ * 10000];   // fc4 partial sums (10.24 MB)

// -------------------- MLP layers 1..3 (small) ----------------------
__global__ void fc1_kernel(const float* __restrict__ pores,
                           const float* __restrict__ W,
                           const float* __restrict__ bias) {
    int idx = blockIdx.x * blockDim.x + threadIdx.x;
    if (idx >= B_SZ * 128) return;
    int b = idx >> 7, j = idx & 127;
    float acc = bias[j];
#pragma unroll
    for (int k = 0; k < 25; k++)
        acc = fmaf(pores[b * 25 + k], W[k * 128 + j], acc);
    g_h1[idx] = fmaxf(acc, 0.0f);
}

__global__ void fc2_kernel(const float* __restrict__ W,
                           const float* __restrict__ bias) {
    int idx = blockIdx.x * blockDim.x + threadIdx.x;
    if (idx >= B_SZ * 256) return;
    int b = idx >> 8, j = idx & 255;
    float acc = bias[j];
#pragma unroll 8
    for (int k = 0; k < 128; k++)
        acc = fmaf(g_h1[b * 128 + k], W[k * 256 + j], acc);
    g_h2[idx] = fmaxf(acc, 0.0f);
}

__global__ void fc3_kernel(const float* __restrict__ W,
                           const float* __restrict__ bias) {
    int idx = blockIdx.x * blockDim.x + threadIdx.x;
    if (idx >= B_SZ * 512) return;
    int b = idx >> 9, j = idx & 511;
    float acc = bias[j];
#pragma unroll 8
    for (int k = 0; k < 256; k++)
        acc = fmaf(g_h2[b * 256 + k], W[k * 512 + j], acc);
    g_h3[idx] = fmaxf(acc, 0.0f);
}

// ---------------- fc4 stage 1: split-K partial sums ----------------
// grid (79, KSPLIT), block 128. Block (bo, bk) covers output cols
// [bo*128, bo*128+128) and k-range [bk*64, bk*64+64). W4 streamed
// coalesced; 8x the DRAM-level parallelism of the fused version.
__global__ __launch_bounds__(128) void fc4_partial_kernel(
    const float* __restrict__ W)     // [512,10000]
{
    __shared__ float h3s[B_SZ * 64];   // 8 KB: h3 chunk for this k-range
    int k0 = blockIdx.y * 64;
    for (int i = threadIdx.x; i < B_SZ * 64; i += blockDim.x) {
        int q = i >> 6, kk = i & 63;
        h3s[i] = g_h3[q * 512 + k0 + kk];
    }
    __syncthreads();

    int o = blockIdx.x * blockDim.x + threadIdx.x;
    if (o >= RESN * RESN) return;

    float acc[B_SZ];
#pragma unroll
    for (int q = 0; q < B_SZ; q++) acc[q] = 0.0f;

    for (int kk = 0; kk < 64; kk++) {
        float w = W[(k0 + kk) * 10000 + o];
#pragma unroll
        for (int q = 0; q < B_SZ; q++)
            acc[q] = fmaf(h3s[q * 64 + kk], w, acc[q]);   // h3s broadcast
    }

    float* dst = g_part + blockIdx.y * (B_SZ * 10000);
#pragma unroll
    for (int q = 0; q < B_SZ; q++)
        dst[q * 10000 + o] = acc[q];
}

// -------- fc4 stage 2: reduce + bias + residual + clamp ------------
__global__ __launch_bounds__(128) void fc4_final_kernel(
    const float* __restrict__ bias,  // [10000]
    const float* __restrict__ pores, // [32,25]
    float* __restrict__ cond)        // [32,10000]
{
    int o = blockIdx.x * blockDim.x + threadIdx.x;
    if (o >= RESN * RESN) return;
    int i = o / RESN, j = o % RESN;
    int pidx = (i / 20) * 5 + (j / 20);
    float bb = bias[o];
#pragma unroll 4
    for (int q = 0; q < B_SZ; q++) {
        float s = bb;
#pragma unroll
        for (int p = 0; p < KSPLIT; p++)
            s += g_part[p * (B_SZ * 10000) + q * 10000 + o];
        float base = 1.0f - pores[q * 25 + pidx];
        cond[q * 10000 + o] = fmaxf(s + base, 0.01f);
    }
}

// ----------------- cluster mbarrier / DSMEM helpers ----------------
__device__ __forceinline__ uint32_t smem_u32(const void* p) {
    uint32_t a;
    asm("{ .reg .u64 t; cvta.to.shared.u64 t, %1; cvt.u32.u64 %0, t; }"
        : "=r"(a) : "l"(p));
    return a;
}

__device__ __forceinline__ void mbar_init(uint32_t mbar, uint32_t count) {
    asm volatile("mbarrier.init.shared.b64 [%0], %1;" :: "r"(mbar), "r"(count) : "memory");
}

// wait with ACQUIRE at CLUSTER scope (we consume peer DSMEM stores)
__device__ __forceinline__ void mbar_wait_cluster(uint32_t mbar, uint32_t parity) {
    asm volatile(
        "{\n\t.reg .pred P;\n\t"
        "WL_%=:\n\t"
        "mbarrier.try_wait.parity.acquire.cluster.shared::cta.b64 P, [%0], %1, 0x989680;\n\t"
        "@P bra.uni WD_%=;\n\t"
        "bra.uni WL_%=;\n\t"
        "WD_%=:\n\t}"
        :: "r"(mbar), "r"(parity) : "memory");
}

// release-arrive on the SAME smem offset in a peer CTA
__device__ __forceinline__ void mbar_arrive_peer(uint32_t local_mbar, uint32_t rank) {
    asm volatile(
        "{\n\t.reg .b32 ra;\n\t"
        "mapa.shared::cluster.u32 ra, %0, %1;\n\t"
        "mbarrier.arrive.release.cluster.shared::cluster.b64 _, [ra];\n\t}"
        :: "r"(local_mbar), "r"(rank) : "memory");
}

__device__ __forceinline__ void dsmem_st_v4(uint32_t local_addr, uint32_t rank, float4 v) {
    asm volatile(
        "{\n\t.reg .b32 ra;\n\t"
        "mapa.shared::cluster.u32 ra, %0, %1;\n\t"
        "st.shared::cluster.v4.f32 [ra], {%2, %3, %4, %5};\n\t}"
        :: "r"(local_addr), "r"(rank), "f"(v.x), "f"(v.y), "f"(v.z), "f"(v.w)
        : "memory");
}

// ------------------- Jacobi: 4-CTA cluster per sample ---------------
// grid = 128 (32 samples x 4 cluster CTAs), 128 threads (125 active).
// Thread (r = tid/5 in [0,25), s = tid%5) owns a 20-col row segment.
// SMEM field double-buffered, 27 rows each: row 0 = top halo, rows
// 1..25 = own, row 26 = bottom halo. Edge rows are PUSHED into the
// neighbor's halo of the next buffer via st.shared::cluster, signaled
// with pairwise mbarriers (5 arrivals = 5 segment threads).
__global__ __launch_bounds__(128, 1) __cluster_dims__(CSIZE, 1, 1)
void jacobi_kernel(const float* __restrict__ cond,   // [32,10000]
                   float* __restrict__ kappa)        // [32]
{
    __shared__ float Tbuf[2][27 * 100];
    __shared__ float partial[5];
    __shared__ uint64_t mbar_up_s, mbar_dn_s;   // arrivals INTO my top/bottom halo

    int tid  = threadIdx.x;
    int rank = blockIdx.x & (CSIZE - 1);
    int b    = blockIdx.x >> 2;
    const float* k = cond + b * 10000;

    bool act = tid < 125;
    int r  = tid / 5;            // local row 0..24
    int s  = tid % 5;
    int c0 = s * 20;
    int rg = rank * RPC + r;     // global row

    uint32_t mbar_up = smem_u32(&mbar_up_s);
    uint32_t mbar_dn = smem_u32(&mbar_dn_s);
    if (tid == 0) { mbar_init(mbar_up, 5); mbar_init(mbar_dn, 5); }

    bool top_edge = act && (r == 0)  && (rank > 0);          // waits mbar_up, pushes up
    bool bot_edge = act && (r == 24) && (rank < CSIZE - 1);  // waits mbar_dn, pushes down

    // ---- per-thread coefficients (registers) ----
    float rN[20], rS[20], rW[20], rE[20], Tc[20];
    if (act) {
        int rm = (rg == 0)  ? 0  : rg - 1;
        int rp = (rg == 99) ? 99 : rg + 1;
#pragma unroll
        for (int j = 0; j < 20; j++) {
            int c  = c0 + j;
            int cm = (c == 0)  ? 0  : c - 1;
            int cp = (c == 99) ? 99 : c + 1;
            float kc = k[rg * 100 + c];
            float kn = 0.5f * (kc + k[rm * 100 + c]);
            float ks = 0.5f * (kc + k[rp * 100 + c]);
            float kw = 0.5f * (kc + k[rg * 100 + cm]);
            float ke = 0.5f * (kc + k[rg * 100 + cp]);
            float inv = 1.0f / (kn + ks + kw + ke + 1e-12f);
            rN[j] = kn * inv; rS[j] = ks * inv;
            rW[j] = kw * inv; rE[j] = ke * inv;
        }
        float tv = 1.0f - (float)rg * (1.0f / 99.0f);
#pragma unroll
        for (int j = 0; j < 20; j++) {
            Tc[j] = tv;
            Tbuf[0][(r + 1) * 100 + c0 + j] = tv;
        }
    }
    // initial halos of buffer 0 (iteration-0 input field is analytic)
    if (tid < 100) {
        int g0 = rank * RPC;
        float hu = (g0 == 0) ? 1.0f : 1.0f - (float)(g0 - 1) * (1.0f / 99.0f);
        float hd = (g0 + RPC >= 100) ? 0.0f : 1.0f - (float)(g0 + RPC) * (1.0f / 99.0f);
        Tbuf[0][0 * 100 + tid]  = hu;
        Tbuf[0][26 * 100 + tid] = hd;
    }
    __syncthreads();
    // mbar init + halos visible cluster-wide before any peer traffic
    asm volatile("barrier.cluster.arrive.aligned;" ::: "memory");
    asm volatile("barrier.cluster.wait.aligned;"   ::: "memory");

    int cur = 0;
    for (int it = 0; it < ITERS; ++it) {
        int nxt = cur ^ 1;
        if (act) {
            if (it > 0) {
                int wp = (it - 1) & 1;
                if (top_edge) mbar_wait_cluster(mbar_up, wp);
                if (bot_edge) mbar_wait_cluster(mbar_dn, wp);
            }
            float* C = Tbuf[cur];
            float* Nx = Tbuf[nxt];
            int base = (r + 1) * 100 + c0;

            float left   = (c0 == 0)  ? Tc[0]  : C[base - 1];
            float rightb = (c0 == 80) ? Tc[19] : C[base + 20];
            const float4* nrow = reinterpret_cast<const float4*>(C + base - 100);
            const float4* srow = reinterpret_cast<const float4*>(C + base + 100);
            float4* orow = reinterpret_cast<float4*>(Nx + base);

            float prev = left;
            float4 outv[5];
#pragma unroll
            for (int m = 0; m < 5; m++) {
                float4 n4 = (rg == 0)  ? make_float4(1.f, 1.f, 1.f, 1.f) : nrow[m];
                float4 s4 = (rg == 99) ? make_float4(0.f, 0.f, 0.f, 0.f) : srow[m];
                float tn[4] = {n4.x, n4.y, n4.z, n4.w};
                float ts[4] = {s4.x, s4.y, s4.z, s4.w};
                float res[4];
#pragma unroll
                for (int jj = 0; jj < 4; jj++) {
                    int j = 4 * m + jj;
                    float right = (j == 19) ? rightb : Tc[j + 1];
                    float old = Tc[j];
                    float v = fmaf(rN[j], tn[jj],
                              fmaf(rS[j], ts[jj],
                              fmaf(rW[j], prev, rE[j] * right)));
                    Tc[j] = v;
                    res[jj] = v;
                    prev = old;
                }
                outv[m] = make_float4(res[0], res[1], res[2], res[3]);
                orow[m] = outv[m];
            }

            // push new edge rows into neighbor halos of THEIR nxt buffer
            if (top_edge) {
                uint32_t dst = smem_u32(&Tbuf[nxt][26 * 100 + c0]);  // above's bottom halo
#pragma unroll
                for (int m = 0; m < 5; m++)
                    dsmem_st_v4(dst + m * 16, rank - 1, outv[m]);
                mbar_arrive_peer(mbar_dn, rank - 1);   // above waits on its mbar_dn
            }
            if (bot_edge) {
                uint32_t dst = smem_u32(&Tbuf[nxt][0 * 100 + c0]);   // below's top halo
#pragma unroll
                for (int m = 0; m < 5; m++)
                    dsmem_st_v4(dst + m * 16, rank + 1, outv[m]);
                mbar_arrive_peer(mbar_up, rank + 1);   // below waits on its mbar_up
            }
        }
        __syncthreads();
        cur ^= 1;
    }

    // kappa from global top row (rank 0 only)
    if (rank == 0) {
        if (act && r == 0) {
            float p = 0.0f;
#pragma unroll
            for (int j = 0; j < 20; j++)
                p += k[c0 + j] * (1.0f - Tc[j]);
            partial[s] = p;
        }
        __syncthreads();
        if (tid == 0)
            kappa[b] = 2.0f * (partial[0] + partial[1] + partial[2] + partial[3] + partial[4]);
    }

    // no CTA may exit while a peer could still push into its SMEM
    asm volatile("barrier.cluster.arrive.aligned;" ::: "memory");
    asm volatile("barrier.cluster.wait.aligned;"   ::: "memory");
}

// --------------------------- launcher ------------------------------
extern "C" void kernel_launch(void* const* d_in, const int* in_sizes, int n_in,
                              void* d_out, int out_size) {
    const float* pores = (const float*)d_in[0];
    const float* W1 = (const float*)d_in[1];
    const float* b1 = (const float*)d_in[2];
    const float* W2 = (const float*)d_in[3];
    const float* b2 = (const float*)d_in[4];
    const float* W3 = (const float*)d_in[5];
    const float* b3 = (const float*)d_in[6];
    const float* W4 = (const float*)d_in[7];
    const float* b4 = (const float*)d_in[8];

    float* out   = (float*)d_out;
    float* kappa = out;          // [32]
    float* cond  = out + B_SZ;   // [32,100,100]

    fc1_kernel<<<(B_SZ * 128 + 255) / 256, 256>>>(pores, W1, b1);
    fc2_kernel<<<(B_SZ * 256 + 255) / 256, 256>>>(W2, b2);
    fc3_kernel<<<(B_SZ * 512 + 255) / 256, 256>>>(W3, b3);
    dim3 g4((10000 + 127) / 128, KSPLIT);
    fc4_partial_kernel<<<g4, 128>>>(W4);
    fc4_final_kernel<<<(10000 + 127) / 128, 128>>>(b4, pores, cond);
    jacobi_kernel<<<B_SZ * CSIZE, 128>>>(cond, kappa);
}